// round 3
// baseline (speedup 1.0000x reference)
#include <cuda_runtime.h>
#include <cuda_bf16.h>
#include <cstdint>

// ---------------- problem constants ----------------
#define B_     16
#define L_     8192
#define IN_    57
#define DM     64
#define DS     32
#define HD     32
#define NH     4
#define DI     128          // EXP*DM
#define DPROJ  324          // 2*DI + 2*DS + NH
#define NL     2
#define OUT_   6
#define Q      64           // chunk length
#define NCH    (L_ / Q)     // 128 chunks
#define NSEG   16           // scan segments
#define CPS    (NCH / NSEG) // 8 chunks per segment
#define BL     (B_ * L_)    // 131072 rows

typedef unsigned long long u64;

// ---------------- scratch (device globals; allocation-free) ----------------
__device__ float g_h [BL * DM];
__device__ float g_X [BL * DI];
__device__ float g_Z [BL * DI];
__device__ float g_y [BL * DI];
__device__ float g_Bm[BL * DS];
__device__ float g_Cm[BL * DS];
__device__ float g_dt[BL * NH];
__device__ float g_la[BL * NH];
__device__ float g_Sd[B_ * NH * NCH * HD * DS];   // chunk delta states
__device__ float g_h0[B_ * NH * NCH * HD * DS];   // segment-local entry states
__device__ float g_aQ[B_ * NH * NCH];             // chunk total decay
__device__ float g_segS[B_ * NH * NSEG * HD * DS];// segment delta states
__device__ float g_segA[B_ * NH * NSEG];          // segment decay product
__device__ float g_segIn[B_ * NH * NSEG * HD * DS];// segment entry states
__device__ double g_pool[B_ * 16 * DM];

// ---------------- helpers ----------------
__device__ __forceinline__ float siluf(float v) { return v / (1.f + __expf(-v)); }
__device__ __forceinline__ float softplusf(float v) { return (v > 20.f) ? v : log1pf(__expf(v)); }

__device__ __forceinline__ u64 pk2(float lo, float hi) {
    u64 r; asm("mov.b64 %0,{%1,%2};" : "=l"(r) : "f"(lo), "f"(hi)); return r;
}
__device__ __forceinline__ float2 upk2(u64 v) {
    float2 t; asm("mov.b64 {%0,%1},%2;" : "=f"(t.x), "=f"(t.y) : "l"(v)); return t;
}
__device__ __forceinline__ u64 ffma2(u64 a, u64 b, u64 c) {
    u64 d; asm("fma.rn.f32x2 %0,%1,%2,%3;" : "=l"(d) : "l"(a), "l"(b), "l"(c)); return d;
}

// ================= K1: linear_in  h = x @ W_in + b_in =================
// 16 rows/block; 256 thr = 64 cols x 4 row-groups (4 rows = 2 u64 pairs each)
__global__ void k_linear_in(const float* __restrict__ x,
                            const float* __restrict__ W,
                            const float* __restrict__ bias) {
    const int row0 = blockIdx.x * 16;
    __shared__ __align__(16) float sxT[IN_][18];   // x tile transposed
    const int tid = threadIdx.x;
    for (int idx = tid; idx < 16 * IN_; idx += 256) {
        int r = idx / IN_, k = idx % IN_;
        sxT[k][r] = x[(size_t)(row0 + r) * IN_ + k];
    }
    __syncthreads();
    const int c = tid & 63;
    const int half = tid >> 6;             // 0..3 -> u64 pairs half*2, half*2+1
    float bc = bias[c];
    u64 bc2 = pk2(bc, bc);
    u64 acc2[2] = {bc2, bc2};
    for (int k = 0; k < IN_; k++) {
        float wv = __ldg(&W[k * DM + c]);
        u64 wv2 = pk2(wv, wv);
        const u64* row2 = reinterpret_cast<const u64*>(&sxT[k][0]);
#pragma unroll
        for (int j = 0; j < 2; j++)
            acc2[j] = ffma2(row2[half * 2 + j], wv2, acc2[j]);
    }
#pragma unroll
    for (int j = 0; j < 2; j++) {
        float2 v = upk2(acc2[j]);
        int r = (half * 2 + j) * 2;
        g_h[(size_t)(row0 + r) * DM + c] = v.x;
        g_h[(size_t)(row0 + r + 1) * DM + c] = v.y;
    }
}

// ================= K2: fused in_proj + activations =================
__global__ void k_inproj(const float* __restrict__ W,      // [NL, DM, DPROJ]
                         const float* __restrict__ bias,   // [NL, DPROJ]
                         const float* __restrict__ dt_bias,// [NL, NH]
                         int l) {
    const int row0 = blockIdx.x * 16;
    __shared__ __align__(16) float shT[DM][18];   // h tile transposed
    const int tid = threadIdx.x;
    for (int idx = tid; idx < 16 * DM; idx += 256) {
        int r = idx >> 6, k = idx & 63;
        shT[k][r] = g_h[(size_t)(row0 + r) * DM + k];
    }
    __syncthreads();
    const float* Wl = W + (size_t)l * DM * DPROJ;
    const float* bl = bias + l * DPROJ;

    for (int pass = 0; pass < 2; pass++) {
        int c = (pass == 0) ? tid : 256 + tid;
        if (c < DPROJ) {
            float bc = bl[c];
            u64 bc2 = pk2(bc, bc);
            u64 acc2[8];
#pragma unroll
            for (int j = 0; j < 8; j++) acc2[j] = bc2;
            for (int k = 0; k < DM; k++) {
                float wv = __ldg(&Wl[(size_t)k * DPROJ + c]);
                u64 wv2 = pk2(wv, wv);
                const u64* row2 = reinterpret_cast<const u64*>(&shT[k][0]);
#pragma unroll
                for (int j = 0; j < 8; j++)
                    acc2[j] = ffma2(row2[j], wv2, acc2[j]);
            }
            float acc[16];
#pragma unroll
            for (int j = 0; j < 8; j++) {
                float2 v = upk2(acc2[j]);
                acc[2 * j] = v.x; acc[2 * j + 1] = v.y;
            }
#pragma unroll
            for (int r = 0; r < 16; r++) {
                size_t row = (size_t)row0 + r;
                float v = acc[r];
                if (c < DI) {
                    g_Z[row * DI + c] = siluf(v);
                } else if (c < 2 * DI) {
                    g_X[row * DI + (c - DI)] = siluf(v);
                } else if (c < 2 * DI + DS) {
                    g_Bm[row * DS + (c - 2 * DI)] = siluf(v);
                } else if (c < 2 * DI + 2 * DS) {
                    g_Cm[row * DS + (c - 2 * DI - DS)] = siluf(v);
                } else {
                    int hh = c - (2 * DI + 2 * DS);
                    g_dt[row * NH + hh] = softplusf(v + dt_bias[l * NH + hh]);
                }
            }
        }
    }
}

// ================= K3: per-chunk summary (Sdelta, aQ, la) =================
__global__ void k_chunk_summary(const float* __restrict__ A_log, int l) {
    const int bx = blockIdx.x;                 // = (b*NH + h)*NCH + ch
    const int ch = bx & (NCH - 1);
    const int h  = (bx >> 7) & 3;
    const int b  = bx >> 9;
    const size_t base = (size_t)b * L_ + (size_t)ch * Q;
    __shared__ __align__(16) float sXT[HD][Q + 2];   // X transposed (p-major)
    __shared__ __align__(16) float sBT[DS][Q + 2];   // B transposed (n-major)
    __shared__ float sla[Q], sw_[Q], sdt[Q];
    const int tid = threadIdx.x;               // 1024 threads

    for (int idx = tid; idx < Q * 32; idx += 1024) {
        int s = idx >> 5, j = idx & 31;
        sXT[j][s] = g_X [(base + s) * DI + h * HD + j];
        sBT[j][s] = g_Bm[(base + s) * DS + j];
    }
    if (tid < Q) sdt[tid] = g_dt[(base + tid) * NH + h];
    __syncthreads();

    const float A = -expf(A_log[l * NH + h]);
    if (tid < Q) {  // warp-parallel inclusive scan of dt*A (2 warps)
        float v = sdt[tid] * A;
#pragma unroll
        for (int o = 1; o < 32; o <<= 1) {
            float u = __shfl_up_sync(0xffffffffu, v, o);
            if ((tid & 31) >= o) v += u;
        }
        sla[tid] = v;
    }
    __syncthreads();
    if (tid >= 32 && tid < 64) sla[tid] += sla[31];
    __syncthreads();
    const float laQ = sla[Q - 1];
    if (tid < Q) {
        g_la[(base + tid) * NH + h] = sla[tid];
        sw_[tid] = sdt[tid] * __expf(laQ - sla[tid]);
    }
    __syncthreads();
    for (int idx = tid; idx < HD * Q; idx += 1024) {
        int j = idx >> 6, s = idx & 63;
        sXT[j][s] *= sw_[s];
    }
    __syncthreads();

    const int p = tid >> 5, n = tid & 31;
    const u64* xrow = reinterpret_cast<const u64*>(&sXT[p][0]);
    const u64* brow = reinterpret_cast<const u64*>(&sBT[n][0]);
    u64 acc2 = pk2(0.f, 0.f);
#pragma unroll
    for (int m = 0; m < Q / 2; m++) acc2 = ffma2(xrow[m], brow[m], acc2);
    float2 t = upk2(acc2);
    g_Sd[(size_t)bx * 1024 + tid] = t.x + t.y;
    if (tid == 0) g_aQ[bx] = __expf(laQ);
}

// ================= K4a: segment-local scan =================
__global__ void k_scan_seg() {
    const int blk = blockIdx.x;        // bh*NSEG + seg   (1024 blocks)
    const int bh = blk >> 4, seg = blk & (NSEG - 1);
    const int tid = threadIdx.x;       // 1024
    const size_t cbase = (size_t)bh * NCH + seg * CPS;
    float hloc = 0.f;
#pragma unroll
    for (int j = 0; j < CPS; j++) {
        size_t o = (cbase + j) * 1024 + tid;
        g_h0[o] = hloc;
        hloc = __ldg(&g_aQ[cbase + j]) * hloc + g_Sd[o];
    }
    g_segS[(size_t)blk * 1024 + tid] = hloc;
    if (tid == 0) {
        float p = 1.f;
#pragma unroll
        for (int j = 0; j < CPS; j++) p *= g_aQ[cbase + j];
        g_segA[blk] = p;
    }
}

// ================= K4b: top-level segment scan =================
__global__ void k_scan_top() {
    const int bh = blockIdx.x;         // 64 blocks
    const int tid = threadIdx.x;       // 1024
    float carry = 0.f;
#pragma unroll
    for (int seg = 0; seg < NSEG; seg++) {
        size_t o = ((size_t)bh * NSEG + seg) * 1024 + tid;
        g_segIn[o] = carry;
        carry = __ldg(&g_segA[bh * NSEG + seg]) * carry + g_segS[o];
    }
}

// ================= K5: chunk output (G, Y, skip, gate) =================
__global__ void k_chunk_output(const float* __restrict__ Dp, int l) {
    const int bx = blockIdx.x;
    const int ch = bx & (NCH - 1);
    const int h  = (bx >> 7) & 3;
    const int b  = bx >> 9;
    const int bhIdx = b * NH + h;
    const size_t base = (size_t)b * L_ + (size_t)ch * Q;
    __shared__ __align__(16) float sXT[HD][Q + 2];     // X transposed
    __shared__ __align__(16) float sC[Q][DS + 2];
    __shared__ __align__(16) float sB[Q][DS + 2];
    __shared__ __align__(16) float sh0[HD][DS + 2];
    __shared__ __align__(16) float sG[Q][Q + 2];
    __shared__ float sla[Q], sdt[Q];
    __shared__ float sprefA;
    const int tid = threadIdx.x;      // 256 threads

    if (tid == 0) {
        float p = 1.f;
        int j0 = ch & (CPS - 1);
        size_t cb = (size_t)bhIdx * NCH + (ch & ~(CPS - 1));
        for (int j = 0; j < j0; j++) p *= g_aQ[cb + j];
        sprefA = p;
    }
    for (int idx = tid; idx < Q * 32; idx += 256) {
        int s = idx >> 5, j = idx & 31;
        sXT[j][s] = g_X [(base + s) * DI + h * HD + j];
        sC[s][j] = g_Cm[(base + s) * DS + j];
        sB[s][j] = g_Bm[(base + s) * DS + j];
    }
    if (tid < Q) {
        sla[tid] = g_la[(base + tid) * NH + h];
        sdt[tid] = g_dt[(base + tid) * NH + h];
    }
    __syncthreads();

    // combined entry state: h0_local + prefA * segIn
    {
        const float pa = sprefA;
        const int seg = ch >> 3;  // CPS=8
        const size_t sio = ((size_t)bhIdx * NSEG + seg) * 1024;
        for (int idx = tid; idx < 1024; idx += 256)
            sh0[idx >> 5][idx & 31] = g_h0[(size_t)bx * 1024 + idx] + pa * g_segIn[sio + idx];
    }

    // ---- G[t][s] = (C_t . B_s) * dt_s * exp(la_t - la_s), masked ----
    {
        const int tt = (tid >> 4) * 4;         // 4 t-rows
        const int s0 = tid & 15;               // s = s0 + 16*j
        u64 a2[4][4];
#pragma unroll
        for (int i = 0; i < 4; i++)
#pragma unroll
            for (int j = 0; j < 4; j++) a2[i][j] = pk2(0.f, 0.f);
        const u64* crow0 = reinterpret_cast<const u64*>(&sC[tt + 0][0]);
        const u64* crow1 = reinterpret_cast<const u64*>(&sC[tt + 1][0]);
        const u64* crow2 = reinterpret_cast<const u64*>(&sC[tt + 2][0]);
        const u64* crow3 = reinterpret_cast<const u64*>(&sC[tt + 3][0]);
        const u64* brow0 = reinterpret_cast<const u64*>(&sB[s0 + 0][0]);
        const u64* brow1 = reinterpret_cast<const u64*>(&sB[s0 + 16][0]);
        const u64* brow2 = reinterpret_cast<const u64*>(&sB[s0 + 32][0]);
        const u64* brow3 = reinterpret_cast<const u64*>(&sB[s0 + 48][0]);
#pragma unroll
        for (int m = 0; m < DS / 2; m++) {
            u64 cv0 = crow0[m], cv1 = crow1[m], cv2 = crow2[m], cv3 = crow3[m];
            u64 bv0 = brow0[m], bv1 = brow1[m], bv2 = brow2[m], bv3 = brow3[m];
            a2[0][0] = ffma2(cv0, bv0, a2[0][0]); a2[0][1] = ffma2(cv0, bv1, a2[0][1]);
            a2[0][2] = ffma2(cv0, bv2, a2[0][2]); a2[0][3] = ffma2(cv0, bv3, a2[0][3]);
            a2[1][0] = ffma2(cv1, bv0, a2[1][0]); a2[1][1] = ffma2(cv1, bv1, a2[1][1]);
            a2[1][2] = ffma2(cv1, bv2, a2[1][2]); a2[1][3] = ffma2(cv1, bv3, a2[1][3]);
            a2[2][0] = ffma2(cv2, bv0, a2[2][0]); a2[2][1] = ffma2(cv2, bv1, a2[2][1]);
            a2[2][2] = ffma2(cv2, bv2, a2[2][2]); a2[2][3] = ffma2(cv2, bv3, a2[2][3]);
            a2[3][0] = ffma2(cv3, bv0, a2[3][0]); a2[3][1] = ffma2(cv3, bv1, a2[3][1]);
            a2[3][2] = ffma2(cv3, bv2, a2[3][2]); a2[3][3] = ffma2(cv3, bv3, a2[3][3]);
        }
#pragma unroll
        for (int i = 0; i < 4; i++) {
            float lat = sla[tt + i];
#pragma unroll
            for (int j = 0; j < 4; j++) {
                int s = s0 + 16 * j;
                float2 v = upk2(a2[i][j]);
                float dot = v.x + v.y;
                sG[tt + i][s] = (s <= tt + i) ? dot * sdt[s] * __expf(lat - sla[s]) : 0.f;
            }
        }
    }
    __syncthreads();

    // ---- Y[t][p] = exp(la_t)*(C_t . h0[p,:]) + sum_s G[t][s]*X[s][p] ----
    {
        const int p = tid & 31;
        const int w = tid >> 5;               // 8 warps, 8 t-rows each
        u64 y2[8];
#pragma unroll
        for (int i = 0; i < 8; i++) y2[i] = pk2(0.f, 0.f);
        const u64* hrow = reinterpret_cast<const u64*>(&sh0[p][0]);
#pragma unroll
        for (int m = 0; m < DS / 2; m++) {
            u64 hv = hrow[m];
#pragma unroll
            for (int i = 0; i < 8; i++) {
                const u64* cr = reinterpret_cast<const u64*>(&sC[w * 8 + i][0]);
                y2[i] = ffma2(cr[m], hv, y2[i]);
            }
        }
        float y[8];
#pragma unroll
        for (int i = 0; i < 8; i++) {
            float2 v = upk2(y2[i]);
            y[i] = (v.x + v.y) * __expf(sla[w * 8 + i]);
            y2[i] = pk2(0.f, 0.f);
        }
        const u64* xrow = reinterpret_cast<const u64*>(&sXT[p][0]);
#pragma unroll
        for (int m = 0; m < Q / 2; m++) {
            u64 xv = xrow[m];
#pragma unroll
            for (int i = 0; i < 8; i++) {
                const u64* gr = reinterpret_cast<const u64*>(&sG[w * 8 + i][0]);
                y2[i] = ffma2(gr[m], xv, y2[i]);
            }
        }
        const float Dh = Dp[l * NH + h];
#pragma unroll
        for (int i = 0; i < 8; i++) {
            float2 v = upk2(y2[i]);
            int t = w * 8 + i;
            size_t o = (base + t) * DI + h * HD + p;
            g_y[o] = (y[i] + v.x + v.y + Dh * sXT[p][t]) * g_Z[o];
        }
    }
}

// ================= K6: out_proj + residual =================
// 16 rows/block; 256 thr = 64 cols x 4 row-groups (4 rows = 2 u64 pairs each)
__global__ void k_outproj(const float* __restrict__ Wo,  // [NL, DI, DM]
                          const float* __restrict__ bo,  // [NL, DM]
                          int l) {
    const int row0 = blockIdx.x * 16;
    __shared__ __align__(16) float sYT[DI][18];
    const int tid = threadIdx.x;
    for (int idx = tid; idx < 16 * DI; idx += 256) {
        int r = idx >> 7, k = idx & 127;
        sYT[k][r] = g_y[(size_t)(row0 + r) * DI + k];
    }
    __syncthreads();
    const int c = tid & 63, half = tid >> 6;  // half: u64 pairs half*2, half*2+1
    const float* Wl = Wo + (size_t)l * DI * DM;
    u64 acc2[2];
#pragma unroll
    for (int j = 0; j < 2; j++) acc2[j] = pk2(0.f, 0.f);
    for (int k = 0; k < DI; k++) {
        float wv = __ldg(&Wl[k * DM + c]);
        u64 wv2 = pk2(wv, wv);
        const u64* row2 = reinterpret_cast<const u64*>(&sYT[k][0]);
#pragma unroll
        for (int j = 0; j < 2; j++)
            acc2[j] = ffma2(row2[half * 2 + j], wv2, acc2[j]);
    }
    const float bc = bo[l * DM + c];
#pragma unroll
    for (int j = 0; j < 2; j++) {
        float2 v = upk2(acc2[j]);
        int r = (half * 2 + j) * 2;
        size_t o0 = (size_t)(row0 + r) * DM + c;
        size_t o1 = (size_t)(row0 + r + 1) * DM + c;
        g_h[o0] = g_h[o0] + v.x + bc;
        g_h[o1] = g_h[o1] + v.y + bc;
    }
}

// ================= K7a: pooling partial sums =================
__global__ void k_pool_a() {
    const int b = blockIdx.x >> 4, seg = blockIdx.x & 15;   // 256 blocks
    const int tid = threadIdx.x;   // 256
    const int d = tid & 63, part = tid >> 6;
    double s = 0.0;
    for (int ll = seg * 512 + part; ll < (seg + 1) * 512; ll += 4)
        s += (double)g_h[((size_t)b * L_ + ll) * DM + d];
    __shared__ double red[4][64];
    red[part][d] = s;
    __syncthreads();
    if (tid < 64)
        g_pool[((size_t)b * 16 + seg) * DM + tid] =
            red[0][tid] + red[1][tid] + red[2][tid] + red[3][tid];
}

// ================= K7b: combine + classifier =================
__global__ void k_pool_cls(const float* __restrict__ cW,
                           const float* __restrict__ cb,
                           float* __restrict__ out) {
    const int b = blockIdx.x;
    const int tid = threadIdx.x;   // 64
    __shared__ double pooled[64];
    double s = 0.0;
    for (int seg = 0; seg < 16; seg++)
        s += g_pool[((size_t)b * 16 + seg) * DM + tid];
    pooled[tid] = s / (double)L_;
    __syncthreads();
    if (tid < OUT_) {
        double acc = (double)cb[tid];
        for (int dd = 0; dd < DM; dd++)
            acc += pooled[dd] * (double)cW[dd * OUT_ + tid];
        out[b * OUT_ + tid] = (float)acc;
    }
}

// ================= launch =================
extern "C" void kernel_launch(void* const* d_in, const int* in_sizes, int n_in,
                              void* d_out, int out_size) {
    const float* x        = (const float*)d_in[0];
    const float* W_in     = (const float*)d_in[1];
    const float* b_in     = (const float*)d_in[2];
    const float* in_proj_W= (const float*)d_in[3];
    const float* in_proj_b= (const float*)d_in[4];
    const float* A_log    = (const float*)d_in[5];
    const float* Dp       = (const float*)d_in[6];
    const float* dt_bias  = (const float*)d_in[7];
    const float* out_proj_W = (const float*)d_in[8];
    const float* out_proj_b = (const float*)d_in[9];
    const float* cls_W    = (const float*)d_in[10];
    const float* cls_b    = (const float*)d_in[11];
    float* out = (float*)d_out;

    k_linear_in<<<BL / 16, 256>>>(x, W_in, b_in);
    for (int l = 0; l < NL; l++) {
        k_inproj<<<BL / 16, 256>>>(in_proj_W, in_proj_b, dt_bias, l);
        k_chunk_summary<<<B_ * NH * NCH, 1024>>>(A_log, l);
        k_scan_seg<<<B_ * NH * NSEG, 1024>>>();
        k_scan_top<<<B_ * NH, 1024>>>();
        k_chunk_output<<<B_ * NH * NCH, 256>>>(Dp, l);
        k_outproj<<<BL / 16, 256>>>(out_proj_W, out_proj_b, l);
    }
    k_pool_a<<<B_ * 16, 256>>>();
    k_pool_cls<<<B_, 64>>>(cls_W, cls_b, out);
}

// round 4
// speedup vs baseline: 1.3106x; 1.3106x over previous
#include <cuda_runtime.h>
#include <cuda_bf16.h>
#include <cstdint>

// ---------------- problem constants ----------------
#define B_     16
#define L_     8192
#define IN_    57
#define DM     64
#define DS     32
#define HD     32
#define NH     4
#define DI     128          // EXP*DM
#define DPROJ  324          // 2*DI + 2*DS + NH
#define NL     2
#define OUT_   6
#define Q      64           // chunk length
#define NCH    (L_ / Q)     // 128 chunks
#define NSEG   16           // scan segments
#define CPS    (NCH / NSEG) // 8 chunks per segment
#define BL     (B_ * L_)    // 131072 rows

// ---------------- scratch (device globals; allocation-free) ----------------
__device__ float g_h [BL * DM];
__device__ float g_X [BL * DI];
__device__ float g_Z [BL * DI];
__device__ float g_y [BL * DI];
__device__ float g_Bm[BL * DS];
__device__ float g_Cm[BL * DS];
__device__ float g_dt[BL * NH];
__device__ float g_la[BL * NH];
__device__ float g_Sd[B_ * NH * NCH * HD * DS];    // chunk delta states
__device__ float g_h0[B_ * NH * NCH * HD * DS];    // segment-local entry states
__device__ float g_aQ[B_ * NH * NCH];              // chunk total decay
__device__ float g_segS[B_ * NH * NSEG * HD * DS]; // segment delta states
__device__ float g_segA[B_ * NH * NSEG];           // segment decay product
__device__ float g_segIn[B_ * NH * NSEG * HD * DS];// segment entry states
__device__ double g_pool[B_ * 16 * DM];

// ---------------- helpers ----------------
__device__ __forceinline__ float siluf(float v) { return v / (1.f + __expf(-v)); }
__device__ __forceinline__ float softplusf(float v) { return (v > 20.f) ? v : log1pf(__expf(v)); }

// ================= K1: linear_in  h = x @ W_in + b_in =================
__global__ void k_linear_in(const float* __restrict__ x,
                            const float* __restrict__ W,
                            const float* __restrict__ bias) {
    const int row0 = blockIdx.x * 16;
    __shared__ float sx[16][IN_ + 1];
    const int tid = threadIdx.x;
    for (int idx = tid; idx < 16 * IN_; idx += 256) {
        int r = idx / IN_, k = idx % IN_;
        sx[r][k] = x[(size_t)(row0 + r) * IN_ + k];
    }
    __syncthreads();
    const int c = tid & 63, q = tid >> 6;
    float bc = bias[c];
    float acc[4] = {bc, bc, bc, bc};
    for (int k = 0; k < IN_; k++) {
        float wv = __ldg(&W[k * DM + c]);
#pragma unroll
        for (int j = 0; j < 4; j++) acc[j] += sx[q * 4 + j][k] * wv;
    }
#pragma unroll
    for (int j = 0; j < 4; j++)
        g_h[(size_t)(row0 + q * 4 + j) * DM + c] = acc[j];
}

// ================= K2: fused in_proj + activations =================
// 32 rows/block, 384 threads (one column each, 324 active), 32 accs/thread
#define IP_ROWS 32
#define IP_THREADS 384
__global__ void k_inproj(const float* __restrict__ W,      // [NL, DM, DPROJ]
                         const float* __restrict__ bias,   // [NL, DPROJ]
                         const float* __restrict__ dt_bias,// [NL, NH]
                         int l) {
    const int row0 = blockIdx.x * IP_ROWS;
    __shared__ __align__(16) float shT[DM][IP_ROWS + 4];   // h tile transposed (64 x 36)
    const int tid = threadIdx.x;
    for (int idx = tid; idx < IP_ROWS * DM; idx += IP_THREADS) {
        int r = idx >> 6, k = idx & 63;
        shT[k][r] = g_h[(size_t)(row0 + r) * DM + k];
    }
    __syncthreads();
    const float* Wl = W + (size_t)l * DM * DPROJ;
    const int c = tid;
    if (c < DPROJ) {
        float bc = bias[l * DPROJ + c];
        float acc[IP_ROWS];
#pragma unroll
        for (int r = 0; r < IP_ROWS; r++) acc[r] = bc;
        for (int k = 0; k < DM; k++) {
            float wv = __ldg(&Wl[(size_t)k * DPROJ + c]);
            const float4* row4 = reinterpret_cast<const float4*>(&shT[k][0]);
#pragma unroll
            for (int qi = 0; qi < IP_ROWS / 4; qi++) {
                float4 v = row4[qi];
                acc[4 * qi + 0] += v.x * wv;
                acc[4 * qi + 1] += v.y * wv;
                acc[4 * qi + 2] += v.z * wv;
                acc[4 * qi + 3] += v.w * wv;
            }
        }
        if (c < DI) {
#pragma unroll
            for (int r = 0; r < IP_ROWS; r++)
                g_Z[((size_t)row0 + r) * DI + c] = siluf(acc[r]);
        } else if (c < 2 * DI) {
            const int cc = c - DI;
#pragma unroll
            for (int r = 0; r < IP_ROWS; r++)
                g_X[((size_t)row0 + r) * DI + cc] = siluf(acc[r]);
        } else if (c < 2 * DI + DS) {
            const int cc = c - 2 * DI;
#pragma unroll
            for (int r = 0; r < IP_ROWS; r++)
                g_Bm[((size_t)row0 + r) * DS + cc] = siluf(acc[r]);
        } else if (c < 2 * DI + 2 * DS) {
            const int cc = c - 2 * DI - DS;
#pragma unroll
            for (int r = 0; r < IP_ROWS; r++)
                g_Cm[((size_t)row0 + r) * DS + cc] = siluf(acc[r]);
        } else {
            const int hh = c - (2 * DI + 2 * DS);
            const float db = dt_bias[l * NH + hh];
#pragma unroll
            for (int r = 0; r < IP_ROWS; r++)
                g_dt[((size_t)row0 + r) * NH + hh] = softplusf(acc[r] + db);
        }
    }
}

// ================= K3: per-chunk summary (Sdelta, aQ, la) =================
__global__ void k_chunk_summary(const float* __restrict__ A_log, int l) {
    const int bx = blockIdx.x;                 // = (b*NH + h)*NCH + ch
    const int ch = bx & (NCH - 1);
    const int h  = (bx >> 7) & 3;
    const int b  = bx >> 9;
    const size_t base = (size_t)b * L_ + (size_t)ch * Q;
    __shared__ float sX[Q][HD];
    __shared__ float sB[Q][DS];
    __shared__ float sla[Q], sw_[Q], sdt[Q];
    const int tid = threadIdx.x;               // 1024 threads

    for (int idx = tid; idx < Q * 32; idx += 1024) {
        int s = idx >> 5, j = idx & 31;
        sX[s][j] = g_X [(base + s) * DI + h * HD + j];
        sB[s][j] = g_Bm[(base + s) * DS + j];
    }
    if (tid < Q) sdt[tid] = g_dt[(base + tid) * NH + h];
    __syncthreads();

    const float A = -expf(A_log[l * NH + h]);
    if (tid < Q) {  // warp-parallel inclusive scan of dt*A (2 warps)
        float v = sdt[tid] * A;
#pragma unroll
        for (int o = 1; o < 32; o <<= 1) {
            float u = __shfl_up_sync(0xffffffffu, v, o);
            if ((tid & 31) >= o) v += u;
        }
        sla[tid] = v;
    }
    __syncthreads();
    if (tid >= 32 && tid < 64) sla[tid] += sla[31];
    __syncthreads();
    const float laQ = sla[Q - 1];
    if (tid < Q) {
        g_la[(base + tid) * NH + h] = sla[tid];
        sw_[tid] = sdt[tid] * __expf(laQ - sla[tid]);
    }
    __syncthreads();
    for (int idx = tid; idx < Q * HD; idx += 1024) {
        int s = idx >> 5;
        sX[s][idx & 31] *= sw_[s];
    }
    __syncthreads();

    const int p = tid >> 5, n = tid & 31;
    float acc = 0.f;
#pragma unroll
    for (int s = 0; s < Q; s++) acc += sX[s][p] * sB[s][n];
    g_Sd[(size_t)bx * 1024 + tid] = acc;
    if (tid == 0) g_aQ[bx] = __expf(laQ);
}

// ================= K4a: segment-local scan =================
__global__ void k_scan_seg() {
    const int blk = blockIdx.x;        // bh*NSEG + seg   (1024 blocks)
    const int bh = blk >> 4, seg = blk & (NSEG - 1);
    const int tid = threadIdx.x;       // 1024
    const size_t cbase = (size_t)bh * NCH + seg * CPS;
    float hloc = 0.f;
#pragma unroll
    for (int j = 0; j < CPS; j++) {
        size_t o = (cbase + j) * 1024 + tid;
        g_h0[o] = hloc;
        hloc = __ldg(&g_aQ[cbase + j]) * hloc + g_Sd[o];
    }
    g_segS[(size_t)blk * 1024 + tid] = hloc;
    if (tid == 0) {
        float p = 1.f;
#pragma unroll
        for (int j = 0; j < CPS; j++) p *= g_aQ[cbase + j];
        g_segA[blk] = p;
    }
}

// ================= K4b: top-level segment scan =================
__global__ void k_scan_top() {
    const int bh = blockIdx.x;         // 64 blocks
    const int tid = threadIdx.x;       // 1024
    float carry = 0.f;
#pragma unroll
    for (int seg = 0; seg < NSEG; seg++) {
        size_t o = ((size_t)bh * NSEG + seg) * 1024 + tid;
        g_segIn[o] = carry;
        carry = __ldg(&g_segA[bh * NSEG + seg]) * carry + g_segS[o];
    }
}

// ================= K5: chunk output (G, Y, skip, gate) =================
__global__ void k_chunk_output(const float* __restrict__ Dp, int l) {
    const int bx = blockIdx.x;
    const int ch = bx & (NCH - 1);
    const int h  = (bx >> 7) & 3;
    const int b  = bx >> 9;
    const int bhIdx = b * NH + h;
    const size_t base = (size_t)b * L_ + (size_t)ch * Q;
    __shared__ float sX[Q][33], sBm[Q][33], sCm[Q][33];
    __shared__ float sh0[HD][33];
    __shared__ float sla[Q], sdt[Q];
    __shared__ float sG[Q][Q + 1];
    __shared__ float sprefA;
    const int tid = threadIdx.x;      // 256 threads

    if (tid == 0) {
        float p = 1.f;
        int j0 = ch & (CPS - 1);
        size_t cb = (size_t)bhIdx * NCH + (size_t)(ch & ~(CPS - 1));
        for (int j = 0; j < j0; j++) p *= g_aQ[cb + j];
        sprefA = p;
    }
    for (int idx = tid; idx < Q * 32; idx += 256) {
        int s = idx >> 5, j = idx & 31;
        sX [s][j] = g_X [(base + s) * DI + h * HD + j];
        sBm[s][j] = g_Bm[(base + s) * DS + j];
        sCm[s][j] = g_Cm[(base + s) * DS + j];
    }
    if (tid < Q) {
        sla[tid] = g_la[(base + tid) * NH + h];
        sdt[tid] = g_dt[(base + tid) * NH + h];
    }
    __syncthreads();

    // combined entry state: h0_local + prefA * segIn
    {
        const float pa = sprefA;
        const int seg = ch >> 3;  // CPS = 8
        const size_t sio = ((size_t)bhIdx * NSEG + seg) * 1024;
        for (int idx = tid; idx < 1024; idx += 256)
            sh0[idx >> 5][idx & 31] = g_h0[(size_t)bx * 1024 + idx] + pa * g_segIn[sio + idx];
    }

    // ---- G[t][s] = (C_t . B_s) * dt_s * exp(la_t - la_s), masked ----
    {
        const int tt = (tid >> 4) * 4;
        const int ss = (tid & 15) * 4;
        float a[4][4];
#pragma unroll
        for (int i = 0; i < 4; i++)
#pragma unroll
            for (int j = 0; j < 4; j++) a[i][j] = 0.f;
#pragma unroll
        for (int n = 0; n < 32; n++) {
            float cv0 = sCm[tt + 0][n], cv1 = sCm[tt + 1][n];
            float cv2 = sCm[tt + 2][n], cv3 = sCm[tt + 3][n];
            float bv0 = sBm[ss + 0][n], bv1 = sBm[ss + 1][n];
            float bv2 = sBm[ss + 2][n], bv3 = sBm[ss + 3][n];
            a[0][0] += cv0 * bv0; a[0][1] += cv0 * bv1; a[0][2] += cv0 * bv2; a[0][3] += cv0 * bv3;
            a[1][0] += cv1 * bv0; a[1][1] += cv1 * bv1; a[1][2] += cv1 * bv2; a[1][3] += cv1 * bv3;
            a[2][0] += cv2 * bv0; a[2][1] += cv2 * bv1; a[2][2] += cv2 * bv2; a[2][3] += cv2 * bv3;
            a[3][0] += cv3 * bv0; a[3][1] += cv3 * bv1; a[3][2] += cv3 * bv2; a[3][3] += cv3 * bv3;
        }
#pragma unroll
        for (int i = 0; i < 4; i++) {
            float lat = sla[tt + i];
#pragma unroll
            for (int j = 0; j < 4; j++) {
                int s = ss + j;
                float g = (s <= tt + i) ? a[i][j] * sdt[s] * __expf(lat - sla[s]) : 0.f;
                sG[tt + i][s] = g;
            }
        }
    }
    __syncthreads();

    // ---- Y[t][p] = exp(la_t)*(C_t . h0[p,:]) + sum_s G[t][s]*X[s][p] ----
    {
        const int p = tid & 31;
        const int w = tid >> 5;               // 8 warps, 8 t-rows each
        float y[8];
#pragma unroll
        for (int i = 0; i < 8; i++) y[i] = 0.f;
#pragma unroll
        for (int n = 0; n < 32; n++) {
            float h0v = sh0[p][n];
#pragma unroll
            for (int i = 0; i < 8; i++) y[i] += sCm[w * 8 + i][n] * h0v;
        }
#pragma unroll
        for (int i = 0; i < 8; i++) y[i] *= __expf(sla[w * 8 + i]);
        for (int s = 0; s < Q; s++) {
            float xv = sX[s][p];
#pragma unroll
            for (int i = 0; i < 8; i++) y[i] += sG[w * 8 + i][s] * xv;
        }
        const float Dh = Dp[l * NH + h];
#pragma unroll
        for (int i = 0; i < 8; i++) {
            int t = w * 8 + i;
            size_t o = (base + t) * DI + h * HD + p;
            g_y[o] = (y[i] + Dh * sX[t][p]) * g_Z[o];
        }
    }
}

// ================= K6: out_proj + residual =================
// 32 rows/block, 256 threads = 64 cols x 4 row-groups of 8 rows
#define OP_ROWS 32
__global__ void k_outproj(const float* __restrict__ Wo,  // [NL, DI, DM]
                          const float* __restrict__ bo,  // [NL, DM]
                          int l) {
    const int row0 = blockIdx.x * OP_ROWS;
    __shared__ __align__(16) float sYT[DI][OP_ROWS + 4];  // y tile transposed (128 x 36)
    const int tid = threadIdx.x;
    for (int idx = tid; idx < OP_ROWS * DI; idx += 256) {
        int r = idx >> 7, k = idx & 127;
        sYT[k][r] = g_y[(size_t)(row0 + r) * DI + k];
    }
    __syncthreads();
    const int c = tid & 63, g = tid >> 6;   // g in 0..3 -> rows g*8 .. g*8+7
    const float* Wl = Wo + (size_t)l * DI * DM;
    float acc[8];
#pragma unroll
    for (int j = 0; j < 8; j++) acc[j] = 0.f;
    for (int k = 0; k < DI; k++) {
        float wv = __ldg(&Wl[k * DM + c]);
        const float4* row4 = reinterpret_cast<const float4*>(&sYT[k][0]);
        float4 v0 = row4[g * 2], v1 = row4[g * 2 + 1];
        acc[0] += v0.x * wv; acc[1] += v0.y * wv; acc[2] += v0.z * wv; acc[3] += v0.w * wv;
        acc[4] += v1.x * wv; acc[5] += v1.y * wv; acc[6] += v1.z * wv; acc[7] += v1.w * wv;
    }
    const float bc = bo[l * DM + c];
#pragma unroll
    for (int j = 0; j < 8; j++) {
        size_t o = (size_t)(row0 + g * 8 + j) * DM + c;
        g_h[o] = g_h[o] + acc[j] + bc;
    }
}

// ================= K7a: pooling partial sums =================
__global__ void k_pool_a() {
    const int b = blockIdx.x >> 4, seg = blockIdx.x & 15;   // 256 blocks
    const int tid = threadIdx.x;   // 256
    const int d = tid & 63, part = tid >> 6;
    double s = 0.0;
    for (int ll = seg * 512 + part; ll < (seg + 1) * 512; ll += 4)
        s += (double)g_h[((size_t)b * L_ + ll) * DM + d];
    __shared__ double red[4][64];
    red[part][d] = s;
    __syncthreads();
    if (tid < 64)
        g_pool[((size_t)b * 16 + seg) * DM + tid] =
            red[0][tid] + red[1][tid] + red[2][tid] + red[3][tid];
}

// ================= K7b: combine + classifier =================
__global__ void k_pool_cls(const float* __restrict__ cW,
                           const float* __restrict__ cb,
                           float* __restrict__ out) {
    const int b = blockIdx.x;
    const int tid = threadIdx.x;   // 64
    __shared__ double pooled[64];
    double s = 0.0;
    for (int seg = 0; seg < 16; seg++)
        s += g_pool[((size_t)b * 16 + seg) * DM + tid];
    pooled[tid] = s / (double)L_;
    __syncthreads();
    if (tid < OUT_) {
        double acc = (double)cb[tid];
        for (int dd = 0; dd < DM; dd++)
            acc += pooled[dd] * (double)cW[dd * OUT_ + tid];
        out[b * OUT_ + tid] = (float)acc;
    }
}

// ================= launch =================
extern "C" void kernel_launch(void* const* d_in, const int* in_sizes, int n_in,
                              void* d_out, int out_size) {
    const float* x        = (const float*)d_in[0];
    const float* W_in     = (const float*)d_in[1];
    const float* b_in     = (const float*)d_in[2];
    const float* in_proj_W= (const float*)d_in[3];
    const float* in_proj_b= (const float*)d_in[4];
    const float* A_log    = (const float*)d_in[5];
    const float* Dp       = (const float*)d_in[6];
    const float* dt_bias  = (const float*)d_in[7];
    const float* out_proj_W = (const float*)d_in[8];
    const float* out_proj_b = (const float*)d_in[9];
    const float* cls_W    = (const float*)d_in[10];
    const float* cls_b    = (const float*)d_in[11];
    float* out = (float*)d_out;

    k_linear_in<<<BL / 16, 256>>>(x, W_in, b_in);
    for (int l = 0; l < NL; l++) {
        k_inproj<<<BL / IP_ROWS, IP_THREADS>>>(in_proj_W, in_proj_b, dt_bias, l);
        k_chunk_summary<<<B_ * NH * NCH, 1024>>>(A_log, l);
        k_scan_seg<<<B_ * NH * NSEG, 1024>>>();
        k_scan_top<<<B_ * NH, 1024>>>();
        k_chunk_output<<<B_ * NH * NCH, 256>>>(Dp, l);
        k_outproj<<<BL / OP_ROWS, 256>>>(out_proj_W, out_proj_b, l);
    }
    k_pool_a<<<B_ * 16, 256>>>();
    k_pool_cls<<<B_, 64>>>(cls_W, cls_b, out);
}

// round 5
// speedup vs baseline: 1.4568x; 1.1115x over previous
#include <cuda_runtime.h>
#include <cuda_bf16.h>
#include <cstdint>

// ---------------- problem constants ----------------
#define B_     16
#define L_     8192
#define IN_    57
#define DM     64
#define DS     32
#define HD     32
#define NH     4
#define DI     128          // EXP*DM
#define DPROJ  324          // 2*DI + 2*DS + NH
#define NL     2
#define OUT_   6
#define Q      64           // chunk length
#define NCH    (L_ / Q)     // 128 chunks
#define NSEG   16           // scan segments
#define CPS    (NCH / NSEG) // 8 chunks per segment
#define BL     (B_ * L_)    // 131072 rows

// ---------------- scratch (device globals; allocation-free) ----------------
__device__ float g_h [BL * DM];
__device__ float g_X [BL * DI];
__device__ float g_Z [BL * DI];
__device__ float g_y [BL * DI];
__device__ float g_Bm[BL * DS];
__device__ float g_Cm[BL * DS];
__device__ float g_dt[BL * NH];
__device__ float g_la[BL * NH];
__device__ float g_Sd[B_ * NH * NCH * HD * DS];    // chunk delta states
__device__ float g_h0[B_ * NH * NCH * HD * DS];    // segment-local entry states
__device__ float g_aQ[B_ * NH * NCH];              // chunk total decay
__device__ float g_segS[B_ * NH * NSEG * HD * DS]; // segment delta states
__device__ float g_segA[B_ * NH * NSEG];           // segment decay product
__device__ float g_segIn[B_ * NH * NSEG * HD * DS];// segment entry states
__device__ double g_pool[B_ * 16 * DM];

// ---------------- helpers ----------------
__device__ __forceinline__ float siluf(float v) { return v / (1.f + __expf(-v)); }
__device__ __forceinline__ float softplusf(float v) { return (v > 20.f) ? v : log1pf(__expf(v)); }

__device__ __forceinline__ unsigned cvt_tf32(float f) {
    unsigned u; asm("cvt.rna.tf32.f32 %0, %1;" : "=r"(u) : "f"(f)); return u;
}
__device__ __forceinline__ void sp32(float v, unsigned& h, unsigned& l) {
    h = cvt_tf32(v);
    l = cvt_tf32(v - __uint_as_float(h));
}
__device__ __forceinline__ void mma_tf32(float* d, const unsigned* a, const unsigned* b) {
    asm volatile("mma.sync.aligned.m16n8k8.row.col.f32.tf32.tf32.f32 "
                 "{%0,%1,%2,%3},{%4,%5,%6,%7},{%8,%9},{%0,%1,%2,%3};"
                 : "+f"(d[0]), "+f"(d[1]), "+f"(d[2]), "+f"(d[3])
                 : "r"(a[0]), "r"(a[1]), "r"(a[2]), "r"(a[3]),
                   "r"(b[0]), "r"(b[1]));
}

// ================= K1: linear_in  h = x @ W_in + b_in =================
__global__ void k_linear_in(const float* __restrict__ x,
                            const float* __restrict__ W,
                            const float* __restrict__ bias) {
    const int row0 = blockIdx.x * 16;
    __shared__ float sx[16][IN_ + 1];
    const int tid = threadIdx.x;
    for (int idx = tid; idx < 16 * IN_; idx += 256) {
        int r = idx / IN_, k = idx % IN_;
        sx[r][k] = x[(size_t)(row0 + r) * IN_ + k];
    }
    __syncthreads();
    const int c = tid & 63, q = tid >> 6;
    float bc = bias[c];
    float acc[4] = {bc, bc, bc, bc};
    for (int k = 0; k < IN_; k++) {
        float wv = __ldg(&W[k * DM + c]);
#pragma unroll
        for (int j = 0; j < 4; j++) acc[j] += sx[q * 4 + j][k] * wv;
    }
#pragma unroll
    for (int j = 0; j < 4; j++)
        g_h[(size_t)(row0 + q * 4 + j) * DM + c] = acc[j];
}

// ================= K2: in_proj via tf32 MMA (3xTF32 split) =================
// 128 rows/block, 256 threads (8 warps x m16 stripes), N looped in 64-col chunks.
#define IPM 128
#define SH_STRIDE 68     // 68 mod 32 = 4  -> A loads conflict-free (4g+tq unique)
#define SW_STRIDE 72     // 72 mod 32 = 8  -> B loads conflict-free (8tq+g unique)
#define IP_SMEM ((IPM * SH_STRIDE + 64 * SW_STRIDE + 384) * 4)

__device__ __forceinline__ void ip_store(int row, int c, float v0, float v1,
                                         const float* __restrict__ dtb) {
    size_t r = (size_t)row;
    if (c < DI) {
        *reinterpret_cast<float2*>(&g_Z[r * DI + c]) = make_float2(siluf(v0), siluf(v1));
    } else if (c < 2 * DI) {
        *reinterpret_cast<float2*>(&g_X[r * DI + (c - DI)]) = make_float2(siluf(v0), siluf(v1));
    } else if (c < 2 * DI + DS) {
        *reinterpret_cast<float2*>(&g_Bm[r * DS + (c - 2 * DI)]) = make_float2(siluf(v0), siluf(v1));
    } else if (c < 2 * DI + 2 * DS) {
        *reinterpret_cast<float2*>(&g_Cm[r * DS + (c - 2 * DI - DS)]) = make_float2(siluf(v0), siluf(v1));
    } else {
        int hh = c - (2 * DI + 2 * DS);
        *reinterpret_cast<float2*>(&g_dt[r * NH + hh]) =
            make_float2(softplusf(v0 + __ldg(&dtb[hh])), softplusf(v1 + __ldg(&dtb[hh + 1])));
    }
}

__global__ void k_inproj_mma(const float* __restrict__ W,      // [NL, DM, DPROJ]
                             const float* __restrict__ bias,   // [NL, DPROJ]
                             const float* __restrict__ dt_bias,// [NL, NH]
                             int l) {
    extern __shared__ float smem[];
    float* sH = smem;                        // IPM x SH_STRIDE
    float* sW = sH + IPM * SH_STRIDE;        // 64 x SW_STRIDE
    float* sBias = sW + 64 * SW_STRIDE;      // 384

    const int row0 = blockIdx.x * IPM;
    const int tid = threadIdx.x;
    const int w = tid >> 5, lane = tid & 31;
    const int g = lane >> 2, tq = lane & 3;
    const float* Wl = W + (size_t)l * DM * DPROJ;
    const float* dtb = dt_bias + l * NH;

    for (int idx = tid; idx < IPM * DM; idx += 256) {
        int r = idx >> 6, k = idx & 63;
        sH[r * SH_STRIDE + k] = g_h[(size_t)(row0 + r) * DM + k];
    }
    for (int idx = tid; idx < 384; idx += 256)
        sBias[idx] = (idx < DPROJ) ? bias[l * DPROJ + idx] : 0.f;
    __syncthreads();

    const int rA0 = (w * 16 + g) * SH_STRIDE;
    const int rA1 = (w * 16 + g + 8) * SH_STRIDE;

    for (int chunk = 0; chunk < 6; chunk++) {
        for (int idx = tid; idx < 64 * 64; idx += 256) {
            int k = idx >> 6, n = idx & 63;
            int c = chunk * 64 + n;
            sW[k * SW_STRIDE + n] = (c < DPROJ) ? __ldg(&Wl[(size_t)k * DPROJ + c]) : 0.f;
        }
        __syncthreads();

        float fa[8][4];
#pragma unroll
        for (int nt = 0; nt < 8; nt++)
#pragma unroll
            for (int j = 0; j < 4; j++) fa[nt][j] = 0.f;

#pragma unroll
        for (int k0 = 0; k0 < 64; k0 += 8) {
            float a0 = sH[rA0 + k0 + tq];
            float a1 = sH[rA1 + k0 + tq];
            float a2 = sH[rA0 + k0 + tq + 4];
            float a3 = sH[rA1 + k0 + tq + 4];
            unsigned ahi[4], alo[4];
            sp32(a0, ahi[0], alo[0]); sp32(a1, ahi[1], alo[1]);
            sp32(a2, ahi[2], alo[2]); sp32(a3, ahi[3], alo[3]);
#pragma unroll
            for (int nt = 0; nt < 8; nt++) {
                float b0 = sW[(k0 + tq) * SW_STRIDE + nt * 8 + g];
                float b1 = sW[(k0 + tq + 4) * SW_STRIDE + nt * 8 + g];
                unsigned bhi[2], blo[2];
                sp32(b0, bhi[0], blo[0]); sp32(b1, bhi[1], blo[1]);
                mma_tf32(fa[nt], ahi, bhi);
                mma_tf32(fa[nt], ahi, blo);
                mma_tf32(fa[nt], alo, bhi);
            }
        }
        __syncthreads();   // all mma reads of sW done before next chunk overwrites

#pragma unroll
        for (int nt = 0; nt < 8; nt++) {
            int cg = chunk * 64 + nt * 8 + 2 * tq;
            if (cg >= DPROJ) continue;
            float b0v = sBias[cg], b1v = sBias[cg + 1];
            int r0 = row0 + w * 16 + g;
            ip_store(r0,     cg, fa[nt][0] + b0v, fa[nt][1] + b1v, dtb);
            ip_store(r0 + 8, cg, fa[nt][2] + b0v, fa[nt][3] + b1v, dtb);
        }
    }
}

// ================= K3: per-chunk summary (Sdelta, aQ, la) =================
__global__ void k_chunk_summary(const float* __restrict__ A_log, int l) {
    const int bx = blockIdx.x;                 // = (b*NH + h)*NCH + ch
    const int ch = bx & (NCH - 1);
    const int h  = (bx >> 7) & 3;
    const int b  = bx >> 9;
    const size_t base = (size_t)b * L_ + (size_t)ch * Q;
    __shared__ float sX[Q][HD];
    __shared__ float sB[Q][DS];
    __shared__ float sla[Q], sw_[Q], sdt[Q];
    const int tid = threadIdx.x;               // 1024 threads

    for (int idx = tid; idx < Q * 32; idx += 1024) {
        int s = idx >> 5, j = idx & 31;
        sX[s][j] = g_X [(base + s) * DI + h * HD + j];
        sB[s][j] = g_Bm[(base + s) * DS + j];
    }
    if (tid < Q) sdt[tid] = g_dt[(base + tid) * NH + h];
    __syncthreads();

    const float A = -expf(A_log[l * NH + h]);
    if (tid < Q) {  // warp-parallel inclusive scan of dt*A (2 warps)
        float v = sdt[tid] * A;
#pragma unroll
        for (int o = 1; o < 32; o <<= 1) {
            float u = __shfl_up_sync(0xffffffffu, v, o);
            if ((tid & 31) >= o) v += u;
        }
        sla[tid] = v;
    }
    __syncthreads();
    if (tid >= 32 && tid < 64) sla[tid] += sla[31];
    __syncthreads();
    const float laQ = sla[Q - 1];
    if (tid < Q) {
        g_la[(base + tid) * NH + h] = sla[tid];
        sw_[tid] = sdt[tid] * __expf(laQ - sla[tid]);
    }
    __syncthreads();
    for (int idx = tid; idx < Q * HD; idx += 1024) {
        int s = idx >> 5;
        sX[s][idx & 31] *= sw_[s];
    }
    __syncthreads();

    const int p = tid >> 5, n = tid & 31;
    float acc = 0.f;
#pragma unroll
    for (int s = 0; s < Q; s++) acc += sX[s][p] * sB[s][n];
    g_Sd[(size_t)bx * 1024 + tid] = acc;
    if (tid == 0) g_aQ[bx] = __expf(laQ);
}

// ================= K4a: segment-local scan =================
__global__ void k_scan_seg() {
    const int blk = blockIdx.x;        // bh*NSEG + seg   (1024 blocks)
    const int bh = blk >> 4, seg = blk & (NSEG - 1);
    const int tid = threadIdx.x;       // 1024
    const size_t cbase = (size_t)bh * NCH + seg * CPS;
    float hloc = 0.f;
#pragma unroll
    for (int j = 0; j < CPS; j++) {
        size_t o = (cbase + j) * 1024 + tid;
        g_h0[o] = hloc;
        hloc = __ldg(&g_aQ[cbase + j]) * hloc + g_Sd[o];
    }
    g_segS[(size_t)blk * 1024 + tid] = hloc;
    if (tid == 0) {
        float p = 1.f;
#pragma unroll
        for (int j = 0; j < CPS; j++) p *= g_aQ[cbase + j];
        g_segA[blk] = p;
    }
}

// ================= K4b: top-level segment scan =================
__global__ void k_scan_top() {
    const int bh = blockIdx.x;         // 64 blocks
    const int tid = threadIdx.x;       // 1024
    float carry = 0.f;
#pragma unroll
    for (int seg = 0; seg < NSEG; seg++) {
        size_t o = ((size_t)bh * NSEG + seg) * 1024 + tid;
        g_segIn[o] = carry;
        carry = __ldg(&g_segA[bh * NSEG + seg]) * carry + g_segS[o];
    }
}

// ================= K5: chunk output (G, Y, skip, gate) =================
__global__ void k_chunk_output(const float* __restrict__ Dp, int l) {
    const int bx = blockIdx.x;
    const int ch = bx & (NCH - 1);
    const int h  = (bx >> 7) & 3;
    const int b  = bx >> 9;
    const int bhIdx = b * NH + h;
    const size_t base = (size_t)b * L_ + (size_t)ch * Q;
    __shared__ float sX[Q][33], sBm[Q][33], sCm[Q][33];
    __shared__ float sh0[HD][33];
    __shared__ float sla[Q], sdt[Q];
    __shared__ float sG[Q][Q + 1];
    __shared__ float sprefA;
    const int tid = threadIdx.x;      // 256 threads

    if (tid == 0) {
        float p = 1.f;
        int j0 = ch & (CPS - 1);
        size_t cb = (size_t)bhIdx * NCH + (size_t)(ch & ~(CPS - 1));
        for (int j = 0; j < j0; j++) p *= g_aQ[cb + j];
        sprefA = p;
    }
    for (int idx = tid; idx < Q * 32; idx += 256) {
        int s = idx >> 5, j = idx & 31;
        sX [s][j] = g_X [(base + s) * DI + h * HD + j];
        sBm[s][j] = g_Bm[(base + s) * DS + j];
        sCm[s][j] = g_Cm[(base + s) * DS + j];
    }
    if (tid < Q) {
        sla[tid] = g_la[(base + tid) * NH + h];
        sdt[tid] = g_dt[(base + tid) * NH + h];
    }
    __syncthreads();

    // combined entry state: h0_local + prefA * segIn
    {
        const float pa = sprefA;
        const int seg = ch >> 3;  // CPS = 8
        const size_t sio = ((size_t)bhIdx * NSEG + seg) * 1024;
        for (int idx = tid; idx < 1024; idx += 256)
            sh0[idx >> 5][idx & 31] = g_h0[(size_t)bx * 1024 + idx] + pa * g_segIn[sio + idx];
    }

    // ---- G[t][s] = (C_t . B_s) * dt_s * exp(la_t - la_s), masked ----
    {
        const int tt = (tid >> 4) * 4;
        const int ss = (tid & 15) * 4;
        float a[4][4];
#pragma unroll
        for (int i = 0; i < 4; i++)
#pragma unroll
            for (int j = 0; j < 4; j++) a[i][j] = 0.f;
#pragma unroll
        for (int n = 0; n < 32; n++) {
            float cv0 = sCm[tt + 0][n], cv1 = sCm[tt + 1][n];
            float cv2 = sCm[tt + 2][n], cv3 = sCm[tt + 3][n];
            float bv0 = sBm[ss + 0][n], bv1 = sBm[ss + 1][n];
            float bv2 = sBm[ss + 2][n], bv3 = sBm[ss + 3][n];
            a[0][0] += cv0 * bv0; a[0][1] += cv0 * bv1; a[0][2] += cv0 * bv2; a[0][3] += cv0 * bv3;
            a[1][0] += cv1 * bv0; a[1][1] += cv1 * bv1; a[1][2] += cv1 * bv2; a[1][3] += cv1 * bv3;
            a[2][0] += cv2 * bv0; a[2][1] += cv2 * bv1; a[2][2] += cv2 * bv2; a[2][3] += cv2 * bv3;
            a[3][0] += cv3 * bv0; a[3][1] += cv3 * bv1; a[3][2] += cv3 * bv2; a[3][3] += cv3 * bv3;
        }
#pragma unroll
        for (int i = 0; i < 4; i++) {
            float lat = sla[tt + i];
#pragma unroll
            for (int j = 0; j < 4; j++) {
                int s = ss + j;
                float g = (s <= tt + i) ? a[i][j] * sdt[s] * __expf(lat - sla[s]) : 0.f;
                sG[tt + i][s] = g;
            }
        }
    }
    __syncthreads();

    // ---- Y[t][p] = exp(la_t)*(C_t . h0[p,:]) + sum_s G[t][s]*X[s][p] ----
    {
        const int p = tid & 31;
        const int w = tid >> 5;               // 8 warps, 8 t-rows each
        float y[8];
#pragma unroll
        for (int i = 0; i < 8; i++) y[i] = 0.f;
#pragma unroll
        for (int n = 0; n < 32; n++) {
            float h0v = sh0[p][n];
#pragma unroll
            for (int i = 0; i < 8; i++) y[i] += sCm[w * 8 + i][n] * h0v;
        }
#pragma unroll
        for (int i = 0; i < 8; i++) y[i] *= __expf(sla[w * 8 + i]);
        for (int s = 0; s < Q; s++) {
            float xv = sX[s][p];
#pragma unroll
            for (int i = 0; i < 8; i++) y[i] += sG[w * 8 + i][s] * xv;
        }
        const float Dh = Dp[l * NH + h];
#pragma unroll
        for (int i = 0; i < 8; i++) {
            int t = w * 8 + i;
            size_t o = (base + t) * DI + h * HD + p;
            g_y[o] = (y[i] + Dh * sX[t][p]) * g_Z[o];
        }
    }
}

// ================= K6: out_proj via tf32 MMA + residual =================
#define OPM 128
#define SY_STRIDE 132    // 132 mod 32 = 4 -> conflict-free A loads
#define OP_SMEM ((OPM * SY_STRIDE + DI * SW_STRIDE + 64) * 4)
__global__ void k_outproj_mma(const float* __restrict__ Wo,  // [NL, DI, DM]
                              const float* __restrict__ bo,  // [NL, DM]
                              int l) {
    extern __shared__ float smem[];
    float* sY = smem;                         // OPM x SY_STRIDE
    float* sW2 = sY + OPM * SY_STRIDE;        // DI x SW_STRIDE
    float* sB2 = sW2 + DI * SW_STRIDE;        // 64

    const int row0 = blockIdx.x * OPM;
    const int tid = threadIdx.x;
    const int w = tid >> 5, lane = tid & 31;
    const int g = lane >> 2, tq = lane & 3;
    const float* Wl = Wo + (size_t)l * DI * DM;

    for (int idx = tid; idx < OPM * DI; idx += 256) {
        int r = idx >> 7, k = idx & 127;
        sY[r * SY_STRIDE + k] = g_y[(size_t)(row0 + r) * DI + k];
    }
    for (int idx = tid; idx < DI * DM; idx += 256) {
        int k = idx >> 6, n = idx & 63;
        sW2[k * SW_STRIDE + n] = __ldg(&Wl[(size_t)k * DM + n]);
    }
    if (tid < 64) sB2[tid] = bo[l * DM + tid];
    __syncthreads();

    const int rA0 = (w * 16 + g) * SY_STRIDE;
    const int rA1 = (w * 16 + g + 8) * SY_STRIDE;

    float fa[8][4];
#pragma unroll
    for (int nt = 0; nt < 8; nt++)
#pragma unroll
        for (int j = 0; j < 4; j++) fa[nt][j] = 0.f;

#pragma unroll 4
    for (int k0 = 0; k0 < DI; k0 += 8) {
        float a0 = sY[rA0 + k0 + tq];
        float a1 = sY[rA1 + k0 + tq];
        float a2 = sY[rA0 + k0 + tq + 4];
        float a3 = sY[rA1 + k0 + tq + 4];
        unsigned ahi[4], alo[4];
        sp32(a0, ahi[0], alo[0]); sp32(a1, ahi[1], alo[1]);
        sp32(a2, ahi[2], alo[2]); sp32(a3, ahi[3], alo[3]);
#pragma unroll
        for (int nt = 0; nt < 8; nt++) {
            float b0 = sW2[(k0 + tq) * SW_STRIDE + nt * 8 + g];
            float b1 = sW2[(k0 + tq + 4) * SW_STRIDE + nt * 8 + g];
            unsigned bhi[2], blo[2];
            sp32(b0, bhi[0], blo[0]); sp32(b1, bhi[1], blo[1]);
            mma_tf32(fa[nt], ahi, bhi);
            mma_tf32(fa[nt], ahi, blo);
            mma_tf32(fa[nt], alo, bhi);
        }
    }

#pragma unroll
    for (int nt = 0; nt < 8; nt++) {
        int c = nt * 8 + 2 * tq;
        float bc0 = sB2[c], bc1 = sB2[c + 1];
        int r0 = row0 + w * 16 + g;
#pragma unroll
        for (int half = 0; half < 2; half++) {
            int r = r0 + half * 8;
            size_t o = (size_t)r * DM + c;
            float2 hv = *reinterpret_cast<float2*>(&g_h[o]);
            hv.x += fa[nt][half * 2 + 0] + bc0;
            hv.y += fa[nt][half * 2 + 1] + bc1;
            *reinterpret_cast<float2*>(&g_h[o]) = hv;
        }
    }
}

// ================= K7a: pooling partial sums =================
__global__ void k_pool_a() {
    const int b = blockIdx.x >> 4, seg = blockIdx.x & 15;   // 256 blocks
    const int tid = threadIdx.x;   // 256
    const int d = tid & 63, part = tid >> 6;
    double s = 0.0;
    for (int ll = seg * 512 + part; ll < (seg + 1) * 512; ll += 4)
        s += (double)g_h[((size_t)b * L_ + ll) * DM + d];
    __shared__ double red[4][64];
    red[part][d] = s;
    __syncthreads();
    if (tid < 64)
        g_pool[((size_t)b * 16 + seg) * DM + tid] =
            red[0][tid] + red[1][tid] + red[2][tid] + red[3][tid];
}

// ================= K7b: combine + classifier =================
__global__ void k_pool_cls(const float* __restrict__ cW,
                           const float* __restrict__ cb,
                           float* __restrict__ out) {
    const int b = blockIdx.x;
    const int tid = threadIdx.x;   // 64
    __shared__ double pooled[64];
    double s = 0.0;
    for (int seg = 0; seg < 16; seg++)
        s += g_pool[((size_t)b * 16 + seg) * DM + tid];
    pooled[tid] = s / (double)L_;
    __syncthreads();
    if (tid < OUT_) {
        double acc = (double)cb[tid];
        for (int dd = 0; dd < DM; dd++)
            acc += pooled[dd] * (double)cW[dd * OUT_ + tid];
        out[b * OUT_ + tid] = (float)acc;
    }
}

// ================= launch =================
extern "C" void kernel_launch(void* const* d_in, const int* in_sizes, int n_in,
                              void* d_out, int out_size) {
    const float* x        = (const float*)d_in[0];
    const float* W_in     = (const float*)d_in[1];
    const float* b_in     = (const float*)d_in[2];
    const float* in_proj_W= (const float*)d_in[3];
    const float* in_proj_b= (const float*)d_in[4];
    const float* A_log    = (const float*)d_in[5];
    const float* Dp       = (const float*)d_in[6];
    const float* dt_bias  = (const float*)d_in[7];
    const float* out_proj_W = (const float*)d_in[8];
    const float* out_proj_b = (const float*)d_in[9];
    const float* cls_W    = (const float*)d_in[10];
    const float* cls_b    = (const float*)d_in[11];
    float* out = (float*)d_out;

    cudaFuncSetAttribute(k_inproj_mma, cudaFuncAttributeMaxDynamicSharedMemorySize, IP_SMEM);
    cudaFuncSetAttribute(k_outproj_mma, cudaFuncAttributeMaxDynamicSharedMemorySize, OP_SMEM);

    k_linear_in<<<BL / 16, 256>>>(x, W_in, b_in);
    for (int l = 0; l < NL; l++) {
        k_inproj_mma<<<BL / IPM, 256, IP_SMEM>>>(in_proj_W, in_proj_b, dt_bias, l);
        k_chunk_summary<<<B_ * NH * NCH, 1024>>>(A_log, l);
        k_scan_seg<<<B_ * NH * NSEG, 1024>>>();
        k_scan_top<<<B_ * NH, 1024>>>();
        k_chunk_output<<<B_ * NH * NCH, 256>>>(Dp, l);
        k_outproj_mma<<<BL / OPM, 256, OP_SMEM>>>(out_proj_W, out_proj_b, l);
    }
    k_pool_a<<<B_ * 16, 256>>>();
    k_pool_cls<<<B_, 64>>>(cls_W, cls_b, out);
}

// round 6
// speedup vs baseline: 1.9912x; 1.3668x over previous
#include <cuda_runtime.h>
#include <cuda_bf16.h>
#include <cstdint>

// ---------------- problem constants ----------------
#define B_     16
#define L_     8192
#define IN_    57
#define DM     64
#define DS     32
#define HD     32
#define NH     4
#define DI     128          // EXP*DM
#define DPROJ  324          // 2*DI + 2*DS + NH
#define NL     2
#define OUT_   6
#define Q      64           // chunk length
#define NCH    (L_ / Q)     // 128 chunks
#define NSEG   16           // scan segments
#define CPS    (NCH / NSEG) // 8 chunks per segment
#define BL     (B_ * L_)    // 131072 rows

// ---------------- scratch (device globals; allocation-free) ----------------
__device__ float g_h [BL * DM];
__device__ float g_X [BL * DI];
__device__ float g_Z [BL * DI];
__device__ float g_y [BL * DI];
__device__ float g_Bm[BL * DS];
__device__ float g_Cm[BL * DS];
__device__ float g_dt[BL * NH];
__device__ float g_la[BL * NH];
__device__ float g_Sd[B_ * NH * NCH * HD * DS];    // chunk delta states
__device__ float g_h0[B_ * NH * NCH * HD * DS];    // segment-local entry states
__device__ float g_aQ[B_ * NH * NCH];              // chunk total decay
__device__ float g_segS[B_ * NH * NSEG * HD * DS]; // segment delta states
__device__ float g_segA[B_ * NH * NSEG];           // segment decay product
__device__ float g_segIn[B_ * NH * NSEG * HD * DS];// segment entry states
__device__ double g_pool[B_ * 16 * DM];

// ---------------- helpers ----------------
__device__ __forceinline__ float siluf(float v) { return v / (1.f + __expf(-v)); }
__device__ __forceinline__ float softplusf(float v) { return (v > 20.f) ? v : log1pf(__expf(v)); }

__device__ __forceinline__ unsigned cvt_tf32(float f) {
    unsigned u; asm("cvt.rna.tf32.f32 %0, %1;" : "=r"(u) : "f"(f)); return u;
}
__device__ __forceinline__ void sp32(float v, unsigned& h, unsigned& l) {
    h = cvt_tf32(v);
    l = cvt_tf32(v - __uint_as_float(h));
}
__device__ __forceinline__ void mma_tf32(float* d, const unsigned* a, const unsigned* b) {
    asm volatile("mma.sync.aligned.m16n8k8.row.col.f32.tf32.tf32.f32 "
                 "{%0,%1,%2,%3},{%4,%5,%6,%7},{%8,%9},{%0,%1,%2,%3};"
                 : "+f"(d[0]), "+f"(d[1]), "+f"(d[2]), "+f"(d[3])
                 : "r"(a[0]), "r"(a[1]), "r"(a[2]), "r"(a[3]),
                   "r"(b[0]), "r"(b[1]));
}

// ================= K1: linear_in  h = x @ W_in + b_in =================
__global__ void k_linear_in(const float* __restrict__ x,
                            const float* __restrict__ W,
                            const float* __restrict__ bias) {
    const int row0 = blockIdx.x * 16;
    __shared__ float sx[16][IN_ + 1];
    const int tid = threadIdx.x;
    for (int idx = tid; idx < 16 * IN_; idx += 256) {
        int r = idx / IN_, k = idx % IN_;
        sx[r][k] = x[(size_t)(row0 + r) * IN_ + k];
    }
    __syncthreads();
    const int c = tid & 63, q = tid >> 6;
    float bc = bias[c];
    float acc[4] = {bc, bc, bc, bc};
    for (int k = 0; k < IN_; k++) {
        float wv = __ldg(&W[k * DM + c]);
#pragma unroll
        for (int j = 0; j < 4; j++) acc[j] += sx[q * 4 + j][k] * wv;
    }
#pragma unroll
    for (int j = 0; j < 4; j++)
        g_h[(size_t)(row0 + q * 4 + j) * DM + c] = acc[j];
}

// ================= K2: in_proj via tf32 MMA (3xTF32 split) =================
#define IPM 128
#define SH_STRIDE 68     // ≡4 mod 32: A-operand conflict-free
#define SW_STRIDE 72     // ≡8 mod 32: B-operand conflict-free
#define IP_SMEM ((IPM * SH_STRIDE + 64 * SW_STRIDE + 384) * 4)

__device__ __forceinline__ void ip_store(int row, int c, float v0, float v1,
                                         const float* __restrict__ dtb) {
    size_t r = (size_t)row;
    if (c < DI) {
        *reinterpret_cast<float2*>(&g_Z[r * DI + c]) = make_float2(siluf(v0), siluf(v1));
    } else if (c < 2 * DI) {
        *reinterpret_cast<float2*>(&g_X[r * DI + (c - DI)]) = make_float2(siluf(v0), siluf(v1));
    } else if (c < 2 * DI + DS) {
        *reinterpret_cast<float2*>(&g_Bm[r * DS + (c - 2 * DI)]) = make_float2(siluf(v0), siluf(v1));
    } else if (c < 2 * DI + 2 * DS) {
        *reinterpret_cast<float2*>(&g_Cm[r * DS + (c - 2 * DI - DS)]) = make_float2(siluf(v0), siluf(v1));
    } else {
        int hh = c - (2 * DI + 2 * DS);
        *reinterpret_cast<float2*>(&g_dt[r * NH + hh]) =
            make_float2(softplusf(v0 + __ldg(&dtb[hh])), softplusf(v1 + __ldg(&dtb[hh + 1])));
    }
}

__global__ void k_inproj_mma(const float* __restrict__ W,
                             const float* __restrict__ bias,
                             const float* __restrict__ dt_bias,
                             int l) {
    extern __shared__ float smem[];
    float* sH = smem;
    float* sW = sH + IPM * SH_STRIDE;
    float* sBias = sW + 64 * SW_STRIDE;

    const int row0 = blockIdx.x * IPM;
    const int tid = threadIdx.x;
    const int w = tid >> 5, lane = tid & 31;
    const int g = lane >> 2, tq = lane & 3;
    const float* Wl = W + (size_t)l * DM * DPROJ;
    const float* dtb = dt_bias + l * NH;

    for (int idx = tid; idx < IPM * DM; idx += 256) {
        int r = idx >> 6, k = idx & 63;
        sH[r * SH_STRIDE + k] = g_h[(size_t)(row0 + r) * DM + k];
    }
    for (int idx = tid; idx < 384; idx += 256)
        sBias[idx] = (idx < DPROJ) ? bias[l * DPROJ + idx] : 0.f;
    __syncthreads();

    const int rA0 = (w * 16 + g) * SH_STRIDE;
    const int rA1 = (w * 16 + g + 8) * SH_STRIDE;

    for (int chunk = 0; chunk < 6; chunk++) {
        for (int idx = tid; idx < 64 * 64; idx += 256) {
            int k = idx >> 6, n = idx & 63;
            int c = chunk * 64 + n;
            sW[k * SW_STRIDE + n] = (c < DPROJ) ? __ldg(&Wl[(size_t)k * DPROJ + c]) : 0.f;
        }
        __syncthreads();

        float fa[8][4];
#pragma unroll
        for (int nt = 0; nt < 8; nt++)
#pragma unroll
            for (int j = 0; j < 4; j++) fa[nt][j] = 0.f;

#pragma unroll
        for (int k0 = 0; k0 < 64; k0 += 8) {
            unsigned ahi[4], alo[4];
            sp32(sH[rA0 + k0 + tq],     ahi[0], alo[0]);
            sp32(sH[rA1 + k0 + tq],     ahi[1], alo[1]);
            sp32(sH[rA0 + k0 + tq + 4], ahi[2], alo[2]);
            sp32(sH[rA1 + k0 + tq + 4], ahi[3], alo[3]);
#pragma unroll
            for (int nt = 0; nt < 8; nt++) {
                unsigned bhi[2], blo[2];
                sp32(sW[(k0 + tq) * SW_STRIDE + nt * 8 + g],     bhi[0], blo[0]);
                sp32(sW[(k0 + tq + 4) * SW_STRIDE + nt * 8 + g], bhi[1], blo[1]);
                mma_tf32(fa[nt], ahi, bhi);
                mma_tf32(fa[nt], ahi, blo);
                mma_tf32(fa[nt], alo, bhi);
            }
        }
        __syncthreads();

#pragma unroll
        for (int nt = 0; nt < 8; nt++) {
            int cg = chunk * 64 + nt * 8 + 2 * tq;
            if (cg >= DPROJ) continue;
            float b0v = sBias[cg], b1v = sBias[cg + 1];
            int r0 = row0 + w * 16 + g;
            ip_store(r0,     cg, fa[nt][0] + b0v, fa[nt][1] + b1v, dtb);
            ip_store(r0 + 8, cg, fa[nt][2] + b0v, fa[nt][3] + b1v, dtb);
        }
    }
}

// ================= K3: per-chunk summary (Sdelta, aQ, la) =================
// 256 threads, 2x2 register blocking with float2 LDS
#define CS_STRIDE 34
__global__ void k_chunk_summary(const float* __restrict__ A_log, int l) {
    const int bx = blockIdx.x;
    const int ch = bx & (NCH - 1);
    const int h  = (bx >> 7) & 3;
    const int b  = bx >> 9;
    const size_t base = (size_t)b * L_ + (size_t)ch * Q;
    __shared__ __align__(8) float sX[Q * CS_STRIDE];
    __shared__ __align__(8) float sB[Q * CS_STRIDE];
    __shared__ float sla[Q], sw_[Q], sdt[Q];
    const int tid = threadIdx.x;               // 256 threads

    for (int idx = tid; idx < Q * 32; idx += 256) {
        int s = idx >> 5, j = idx & 31;
        sX[s * CS_STRIDE + j] = g_X [(base + s) * DI + h * HD + j];
        sB[s * CS_STRIDE + j] = g_Bm[(base + s) * DS + j];
    }
    if (tid < Q) sdt[tid] = g_dt[(base + tid) * NH + h];
    __syncthreads();

    const float A = -expf(A_log[l * NH + h]);
    if (tid < Q) {
        float v = sdt[tid] * A;
#pragma unroll
        for (int o = 1; o < 32; o <<= 1) {
            float u = __shfl_up_sync(0xffffffffu, v, o);
            if ((tid & 31) >= o) v += u;
        }
        sla[tid] = v;
    }
    __syncthreads();
    if (tid >= 32 && tid < 64) sla[tid] += sla[31];
    __syncthreads();
    const float laQ = sla[Q - 1];
    if (tid < Q) {
        g_la[(base + tid) * NH + h] = sla[tid];
        sw_[tid] = sdt[tid] * __expf(laQ - sla[tid]);
    }
    __syncthreads();
    for (int idx = tid; idx < Q * HD; idx += 256) {
        int s = idx >> 5;
        sX[s * CS_STRIDE + (idx & 31)] *= sw_[s];
    }
    __syncthreads();

    // Sd[p][n] = sum_s Xw[s][p] * B[s][n]; 2x2 per thread
    const int p0 = (tid >> 4) * 2, n0 = (tid & 15) * 2;
    float a00 = 0.f, a01 = 0.f, a10 = 0.f, a11 = 0.f;
#pragma unroll 8
    for (int s = 0; s < Q; s++) {
        float2 xv = *reinterpret_cast<const float2*>(&sX[s * CS_STRIDE + p0]);
        float2 bv = *reinterpret_cast<const float2*>(&sB[s * CS_STRIDE + n0]);
        a00 += xv.x * bv.x; a01 += xv.x * bv.y;
        a10 += xv.y * bv.x; a11 += xv.y * bv.y;
    }
    float* dst = &g_Sd[(size_t)bx * 1024];
    *reinterpret_cast<float2*>(&dst[p0 * 32 + n0])       = make_float2(a00, a01);
    *reinterpret_cast<float2*>(&dst[(p0 + 1) * 32 + n0]) = make_float2(a10, a11);
    if (tid == 0) g_aQ[bx] = __expf(laQ);
}

// ================= K4a: segment-local scan =================
__global__ void k_scan_seg() {
    const int blk = blockIdx.x;
    const int bh = blk >> 4, seg = blk & (NSEG - 1);
    const int tid = threadIdx.x;       // 1024
    const size_t cbase = (size_t)bh * NCH + seg * CPS;
    float hloc = 0.f;
#pragma unroll
    for (int j = 0; j < CPS; j++) {
        size_t o = (cbase + j) * 1024 + tid;
        g_h0[o] = hloc;
        hloc = __ldg(&g_aQ[cbase + j]) * hloc + g_Sd[o];
    }
    g_segS[(size_t)blk * 1024 + tid] = hloc;
    if (tid == 0) {
        float p = 1.f;
#pragma unroll
        for (int j = 0; j < CPS; j++) p *= g_aQ[cbase + j];
        g_segA[blk] = p;
    }
}

// ================= K4b: top-level segment scan =================
__global__ void k_scan_top() {
    const int bh = blockIdx.x;         // 64 blocks
    const int tid = threadIdx.x;       // 1024
    float carry = 0.f;
#pragma unroll
    for (int seg = 0; seg < NSEG; seg++) {
        size_t o = ((size_t)bh * NSEG + seg) * 1024 + tid;
        g_segIn[o] = carry;
        carry = __ldg(&g_segA[bh * NSEG + seg]) * carry + g_segS[o];
    }
}

// ================= K5: chunk output via tf32 MMA =================
// strides: A-operand arrays ≡4 mod 32, B-operand arrays ≡8 mod 32
#define SXO 40   // sX  [64][40]  (B-operand; also epilogue)
#define SBC 36   // sB, sC, sh0   (sB: B-op with col=g pattern; sC: A-op; sh0: B-op col=g)
#define SGS 68   // sG  [64][68]  (A-operand)
#define CO_SMEM ((Q*SXO + Q*SBC + Q*SBC + HD*SBC + Q*SGS + 3*Q) * 4)

__global__ void k_chunk_output_mma(const float* __restrict__ Dp, int l) {
    extern __shared__ float sm[];
    float* sX  = sm;                     // [64][SXO]
    float* sB  = sX + Q * SXO;           // [64][SBC]
    float* sC  = sB + Q * SBC;           // [64][SBC]  (becomes Ce in-place)
    float* sh0 = sC + Q * SBC;           // [32][SBC]
    float* sG  = sh0 + HD * SBC;         // [64][SGS]
    float* sla = sG + Q * SGS;           // [64]
    float* sdt = sla + Q;                // [64]
    float* sE  = sdt + Q;                // [64] exp(la_t)
    __shared__ float sprefA;

    const int bx = blockIdx.x;
    const int ch = bx & (NCH - 1);
    const int h  = (bx >> 7) & 3;
    const int b  = bx >> 9;
    const int bhIdx = b * NH + h;
    const size_t base = (size_t)b * L_ + (size_t)ch * Q;
    const int tid = threadIdx.x;         // 256
    const int w = tid >> 5, lane = tid & 31;
    const int g = lane >> 2, tq = lane & 3;
    const int mrow = (w & 3) * 16;       // M stripe (t rows)

    if (tid == 0) {
        float p = 1.f;
        int j0 = ch & (CPS - 1);
        size_t cb = (size_t)bhIdx * NCH + (size_t)(ch & ~(CPS - 1));
        for (int j = 0; j < j0; j++) p *= g_aQ[cb + j];
        sprefA = p;
    }
    for (int idx = tid; idx < Q * 32; idx += 256) {
        int s = idx >> 5, j = idx & 31;
        sX[s * SXO + j] = g_X [(base + s) * DI + h * HD + j];
        sB[s * SBC + j] = g_Bm[(base + s) * DS + j];
        sC[s * SBC + j] = g_Cm[(base + s) * DS + j];
    }
    if (tid < Q) {
        float la = g_la[(base + tid) * NH + h];
        sla[tid] = la;
        sdt[tid] = g_dt[(base + tid) * NH + h];
        sE[tid] = __expf(la);
    }
    __syncthreads();

    // combined entry state into sh0[p][n]
    {
        const float pa = sprefA;
        const int seg = ch >> 3;
        const size_t sio = ((size_t)bhIdx * NSEG + seg) * 1024;
        for (int idx = tid; idx < 1024; idx += 256)
            sh0[(idx >> 5) * SBC + (idx & 31)] =
                g_h0[(size_t)bx * 1024 + idx] + pa * g_segIn[sio + idx];
    }
    __syncthreads();

    // ---- Phase 1: G = C . B^T  (M=64 t, N=64 s, K=32 n) ----
    // warp w: m-stripe mrow, s-half shalf (32 wide, 4 n-tiles)
    const int shalf = (w >> 2) * 32;
    float ga[4][4];
#pragma unroll
    for (int nt = 0; nt < 4; nt++)
#pragma unroll
        for (int j = 0; j < 4; j++) ga[nt][j] = 0.f;

#pragma unroll
    for (int k0 = 0; k0 < 32; k0 += 8) {
        unsigned ahi[4], alo[4];
        sp32(sC[(mrow + g) * SBC + k0 + tq],         ahi[0], alo[0]);
        sp32(sC[(mrow + g + 8) * SBC + k0 + tq],     ahi[1], alo[1]);
        sp32(sC[(mrow + g) * SBC + k0 + tq + 4],     ahi[2], alo[2]);
        sp32(sC[(mrow + g + 8) * SBC + k0 + tq + 4], ahi[3], alo[3]);
#pragma unroll
        for (int nt = 0; nt < 4; nt++) {
            int sc = shalf + nt * 8 + g;
            unsigned bhi[2], blo[2];
            sp32(sB[sc * SBC + k0 + tq],     bhi[0], blo[0]);
            sp32(sB[sc * SBC + k0 + tq + 4], bhi[1], blo[1]);
            mma_tf32(ga[nt], ahi, bhi);
            mma_tf32(ga[nt], ahi, blo);
            mma_tf32(ga[nt], alo, bhi);
        }
    }
    __syncthreads();   // everyone done reading sC/sB in MMA

    // ---- Phase 2: mask+exp G into sG; scale sC -> Ce in place ----
#pragma unroll
    for (int nt = 0; nt < 4; nt++) {
        int s0 = shalf + nt * 8 + 2 * tq;
        int t0 = mrow + g, t1 = mrow + g + 8;
        float la0 = sla[t0], la1 = sla[t1];
        float d0 = sdt[s0], d1 = sdt[s0 + 1];
        float ls0 = sla[s0], ls1 = sla[s0 + 1];
        sG[t0 * SGS + s0]     = (s0 <= t0)     ? ga[nt][0] * d0 * __expf(la0 - ls0) : 0.f;
        sG[t0 * SGS + s0 + 1] = (s0 + 1 <= t0) ? ga[nt][1] * d1 * __expf(la0 - ls1) : 0.f;
        sG[t1 * SGS + s0]     = (s0 <= t1)     ? ga[nt][2] * d0 * __expf(la1 - ls0) : 0.f;
        sG[t1 * SGS + s0 + 1] = (s0 + 1 <= t1) ? ga[nt][3] * d1 * __expf(la1 - ls1) : 0.f;
    }
    for (int idx = tid; idx < Q * 32; idx += 256) {
        int t = idx >> 5;
        sC[t * SBC + (idx & 31)] *= sE[t];
    }
    __syncthreads();

    // ---- Phase 3: Y = G.X (k=64) + Ce.h0^T (k=32); M=64 t, N=32 p ----
    const int phalf = (w >> 2) * 16;
    float fa[2][4];
#pragma unroll
    for (int nt = 0; nt < 2; nt++)
#pragma unroll
        for (int j = 0; j < 4; j++) fa[nt][j] = 0.f;

#pragma unroll
    for (int k0 = 0; k0 < Q; k0 += 8) {
        unsigned ahi[4], alo[4];
        sp32(sG[(mrow + g) * SGS + k0 + tq],         ahi[0], alo[0]);
        sp32(sG[(mrow + g + 8) * SGS + k0 + tq],     ahi[1], alo[1]);
        sp32(sG[(mrow + g) * SGS + k0 + tq + 4],     ahi[2], alo[2]);
        sp32(sG[(mrow + g + 8) * SGS + k0 + tq + 4], ahi[3], alo[3]);
#pragma unroll
        for (int nt = 0; nt < 2; nt++) {
            int pc = phalf + nt * 8 + g;
            unsigned bhi[2], blo[2];
            sp32(sX[(k0 + tq) * SXO + pc],     bhi[0], blo[0]);
            sp32(sX[(k0 + tq + 4) * SXO + pc], bhi[1], blo[1]);
            mma_tf32(fa[nt], ahi, bhi);
            mma_tf32(fa[nt], ahi, blo);
            mma_tf32(fa[nt], alo, bhi);
        }
    }
#pragma unroll
    for (int k0 = 0; k0 < 32; k0 += 8) {
        unsigned ahi[4], alo[4];
        sp32(sC[(mrow + g) * SBC + k0 + tq],         ahi[0], alo[0]);
        sp32(sC[(mrow + g + 8) * SBC + k0 + tq],     ahi[1], alo[1]);
        sp32(sC[(mrow + g) * SBC + k0 + tq + 4],     ahi[2], alo[2]);
        sp32(sC[(mrow + g + 8) * SBC + k0 + tq + 4], ahi[3], alo[3]);
#pragma unroll
        for (int nt = 0; nt < 2; nt++) {
            int pc = phalf + nt * 8 + g;
            unsigned bhi[2], blo[2];
            sp32(sh0[pc * SBC + k0 + tq],     bhi[0], blo[0]);
            sp32(sh0[pc * SBC + k0 + tq + 4], bhi[1], blo[1]);
            mma_tf32(fa[nt], ahi, bhi);
            mma_tf32(fa[nt], ahi, blo);
            mma_tf32(fa[nt], alo, bhi);
        }
    }

    // ---- Epilogue: D-skip + z-gate, store ----
    const float Dh = Dp[l * NH + h];
#pragma unroll
    for (int nt = 0; nt < 2; nt++) {
        int pc = phalf + nt * 8 + 2 * tq;
#pragma unroll
        for (int half = 0; half < 2; half++) {
            int t = mrow + g + half * 8;
            size_t o = (base + t) * DI + h * HD + pc;
            float x0 = sX[t * SXO + pc], x1 = sX[t * SXO + pc + 1];
            float2 z = *reinterpret_cast<const float2*>(&g_Z[o]);
            float2 r;
            r.x = (fa[nt][half * 2 + 0] + Dh * x0) * z.x;
            r.y = (fa[nt][half * 2 + 1] + Dh * x1) * z.y;
            *reinterpret_cast<float2*>(&g_y[o]) = r;
        }
    }
}

// ================= K6: out_proj via tf32 MMA + residual =================
#define OPM 128
#define SY_STRIDE 132    // ≡4 mod 32
#define OP_SMEM ((OPM * SY_STRIDE + DI * SW_STRIDE + 64) * 4)
__global__ void k_outproj_mma(const float* __restrict__ Wo,
                              const float* __restrict__ bo,
                              int l) {
    extern __shared__ float smem[];
    float* sY = smem;
    float* sW2 = sY + OPM * SY_STRIDE;
    float* sB2 = sW2 + DI * SW_STRIDE;

    const int row0 = blockIdx.x * OPM;
    const int tid = threadIdx.x;
    const int w = tid >> 5, lane = tid & 31;
    const int g = lane >> 2, tq = lane & 3;
    const float* Wl = Wo + (size_t)l * DI * DM;

    for (int idx = tid; idx < OPM * DI; idx += 256) {
        int r = idx >> 7, k = idx & 127;
        sY[r * SY_STRIDE + k] = g_y[(size_t)(row0 + r) * DI + k];
    }
    for (int idx = tid; idx < DI * DM; idx += 256) {
        int k = idx >> 6, n = idx & 63;
        sW2[k * SW_STRIDE + n] = __ldg(&Wl[(size_t)k * DM + n]);
    }
    if (tid < 64) sB2[tid] = bo[l * DM + tid];
    __syncthreads();

    const int rA0 = (w * 16 + g) * SY_STRIDE;
    const int rA1 = (w * 16 + g + 8) * SY_STRIDE;

    float fa[8][4];
#pragma unroll
    for (int nt = 0; nt < 8; nt++)
#pragma unroll
        for (int j = 0; j < 4; j++) fa[nt][j] = 0.f;

#pragma unroll 4
    for (int k0 = 0; k0 < DI; k0 += 8) {
        unsigned ahi[4], alo[4];
        sp32(sY[rA0 + k0 + tq],     ahi[0], alo[0]);
        sp32(sY[rA1 + k0 + tq],     ahi[1], alo[1]);
        sp32(sY[rA0 + k0 + tq + 4], ahi[2], alo[2]);
        sp32(sY[rA1 + k0 + tq + 4], ahi[3], alo[3]);
#pragma unroll
        for (int nt = 0; nt < 8; nt++) {
            unsigned bhi[2], blo[2];
            sp32(sW2[(k0 + tq) * SW_STRIDE + nt * 8 + g],     bhi[0], blo[0]);
            sp32(sW2[(k0 + tq + 4) * SW_STRIDE + nt * 8 + g], bhi[1], blo[1]);
            mma_tf32(fa[nt], ahi, bhi);
            mma_tf32(fa[nt], ahi, blo);
            mma_tf32(fa[nt], alo, bhi);
        }
    }

#pragma unroll
    for (int nt = 0; nt < 8; nt++) {
        int c = nt * 8 + 2 * tq;
        float bc0 = sB2[c], bc1 = sB2[c + 1];
        int r0 = row0 + w * 16 + g;
#pragma unroll
        for (int half = 0; half < 2; half++) {
            int r = r0 + half * 8;
            size_t o = (size_t)r * DM + c;
            float2 hv = *reinterpret_cast<float2*>(&g_h[o]);
            hv.x += fa[nt][half * 2 + 0] + bc0;
            hv.y += fa[nt][half * 2 + 1] + bc1;
            *reinterpret_cast<float2*>(&g_h[o]) = hv;
        }
    }
}

// ================= K7a: pooling partial sums =================
__global__ void k_pool_a() {
    const int b = blockIdx.x >> 4, seg = blockIdx.x & 15;
    const int tid = threadIdx.x;   // 256
    const int d = tid & 63, part = tid >> 6;
    double s = 0.0;
    for (int ll = seg * 512 + part; ll < (seg + 1) * 512; ll += 4)
        s += (double)g_h[((size_t)b * L_ + ll) * DM + d];
    __shared__ double red[4][64];
    red[part][d] = s;
    __syncthreads();
    if (tid < 64)
        g_pool[((size_t)b * 16 + seg) * DM + tid] =
            red[0][tid] + red[1][tid] + red[2][tid] + red[3][tid];
}

// ================= K7b: combine + classifier =================
__global__ void k_pool_cls(const float* __restrict__ cW,
                           const float* __restrict__ cb,
                           float* __restrict__ out) {
    const int b = blockIdx.x;
    const int tid = threadIdx.x;   // 64
    __shared__ double pooled[64];
    double s = 0.0;
    for (int seg = 0; seg < 16; seg++)
        s += g_pool[((size_t)b * 16 + seg) * DM + tid];
    pooled[tid] = s / (double)L_;
    __syncthreads();
    if (tid < OUT_) {
        double acc = (double)cb[tid];
        for (int dd = 0; dd < DM; dd++)
            acc += pooled[dd] * (double)cW[dd * OUT_ + tid];
        out[b * OUT_ + tid] = (float)acc;
    }
}

// ================= launch =================
extern "C" void kernel_launch(void* const* d_in, const int* in_sizes, int n_in,
                              void* d_out, int out_size) {
    const float* x        = (const float*)d_in[0];
    const float* W_in     = (const float*)d_in[1];
    const float* b_in     = (const float*)d_in[2];
    const float* in_proj_W= (const float*)d_in[3];
    const float* in_proj_b= (const float*)d_in[4];
    const float* A_log    = (const float*)d_in[5];
    const float* Dp       = (const float*)d_in[6];
    const float* dt_bias  = (const float*)d_in[7];
    const float* out_proj_W = (const float*)d_in[8];
    const float* out_proj_b = (const float*)d_in[9];
    const float* cls_W    = (const float*)d_in[10];
    const float* cls_b    = (const float*)d_in[11];
    float* out = (float*)d_out;

    cudaFuncSetAttribute(k_inproj_mma, cudaFuncAttributeMaxDynamicSharedMemorySize, IP_SMEM);
    cudaFuncSetAttribute(k_outproj_mma, cudaFuncAttributeMaxDynamicSharedMemorySize, OP_SMEM);
    cudaFuncSetAttribute(k_chunk_output_mma, cudaFuncAttributeMaxDynamicSharedMemorySize, CO_SMEM);

    k_linear_in<<<BL / 16, 256>>>(x, W_in, b_in);
    for (int l = 0; l < NL; l++) {
        k_inproj_mma<<<BL / IPM, 256, IP_SMEM>>>(in_proj_W, in_proj_b, dt_bias, l);
        k_chunk_summary<<<B_ * NH * NCH, 256>>>(A_log, l);
        k_scan_seg<<<B_ * NH * NSEG, 1024>>>();
        k_scan_top<<<B_ * NH, 1024>>>();
        k_chunk_output_mma<<<B_ * NH * NCH, 256, CO_SMEM>>>(Dp, l);
        k_outproj_mma<<<BL / OPM, 256, OP_SMEM>>>(out_proj_W, out_proj_b, l);
    }
    k_pool_a<<<B_ * 16, 256>>>();
    k_pool_cls<<<B_, 64>>>(cls_W, cls_b, out);
}